// round 8
// baseline (speedup 1.0000x reference)
#include <cuda_runtime.h>

// Problem constants (fixed shapes from the reference setup)
#define NB   16      // batch
#define NT   128     // time
#define NHWC 25088   // 56*56*8 floats per frame
#define NS4  6272    // NHWC / 4 (float4 strips per frame)
#define NC   8       // channels
#define KCH  4       // time chunks
#define TC   (NT / KCH)             // 32 frames per chunk
#define BT   224                    // block threads; NS4 = 28 * 224 exactly
#define NW   (BT / 32)              // 7 warps
#define NBLK_S (NS4 / BT)           // 28 blocks over the spatial strip
#define SLOTS_PER_B (KCH * NBLK_S)  // 112
#define NBLKS  (NB * SLOTS_PER_B)   // 1792 total blocks
#define NFLD   17                   // 8 act + 8 tot + 1 ttv

// Scratch (no device allocation allowed -> __device__ globals).
// FIELD-MAJOR layout: g_part[field][slot] -> coalesced tail reads.
// Every block writes all its fields every launch => no zeroing needed.
// g_done/g_fin self-reset each launch => graph-replay deterministic.
__device__ float        g_part[NFLD][NBLKS];
__device__ unsigned int g_done;
__device__ unsigned int g_fin;

__global__ __launch_bounds__(BT) void reduce_kernel(const float4* __restrict__ x,
                                                    const int* __restrict__ length) {
    // Fire the PDL trigger IMMEDIATELY: the secondary kernel launches and ramps
    // while this grid streams. Data readiness is carried by g_done, not by the
    // trigger's memory semantics.
    cudaTriggerProgrammaticLaunchCompletion();

    const int s4    = blockIdx.x * BT + threadIdx.x;   // always < NS4
    const int b     = blockIdx.z;
    const int chunk = blockIdx.y;
    const int len   = __ldg(&length[b]);
    const int t0    = chunk * TC;
    const float4* base = x + (size_t)b * NT * NS4 + s4;

    float ax = 0.f, ay = 0.f, az = 0.f, aw = 0.f;   // active sums (4 channels)
    float tx = 0.f, ty = 0.f, tz = 0.f, tw = 0.f;   // total sums
    float ttv = 0.f;
    float px = 0.f, py = 0.f, pz = 0.f, pw = 0.f;   // previous masked frame

    if (t0 > 0 && (t0 - 1) < len) {
        float4 p = __ldcs(&base[(size_t)(t0 - 1) * NS4]);
        px = p.x; py = p.y; pz = p.z; pw = p.w;
    }
    #pragma unroll 8
    for (int t = t0; t < t0 + TC; ++t) {
        float4 v = __ldcs(&base[(size_t)t * NS4]);
        tx += v.x; ty += v.y; tz += v.z; tw += v.w;
        float cx, cy, cz, cw;
        if (t < len) {
            cx = v.x; cy = v.y; cz = v.z; cw = v.w;
            ax += v.x; ay += v.y; az += v.z; aw += v.w;
        } else {
            cx = 0.f; cy = 0.f; cz = 0.f; cw = 0.f;
        }
        if (t > 0) {   // skip only the global t=0 (chunk 0, first iter)
            ttv += fabsf(cx - px) + fabsf(cy - py) + fabsf(cz - pz) + fabsf(cw - pw);
        }
        px = cx; py = cy; pz = cz; pw = cw;
    }

    // --- block reduction ---
    #pragma unroll
    for (int m = 16; m >= 1; m >>= 1)
        ttv += __shfl_xor_sync(0xffffffffu, ttv, m);
    // Parity-preserving reduce: even lanes hold channels 0-3, odd lanes 4-7
    #pragma unroll
    for (int m = 2; m <= 16; m <<= 1) {
        ax += __shfl_xor_sync(0xffffffffu, ax, m);
        ay += __shfl_xor_sync(0xffffffffu, ay, m);
        az += __shfl_xor_sync(0xffffffffu, az, m);
        aw += __shfl_xor_sync(0xffffffffu, aw, m);
        tx += __shfl_xor_sync(0xffffffffu, tx, m);
        ty += __shfl_xor_sync(0xffffffffu, ty, m);
        tz += __shfl_xor_sync(0xffffffffu, tz, m);
        tw += __shfl_xor_sync(0xffffffffu, tw, m);
    }

    __shared__ float sh_a[NW][NC];
    __shared__ float sh_t[NW][NC];
    __shared__ float sh_v[NW];
    const int w = threadIdx.x >> 5, lane = threadIdx.x & 31;
    if (lane == 0) {
        sh_a[w][0] = ax; sh_a[w][1] = ay; sh_a[w][2] = az; sh_a[w][3] = aw;
        sh_t[w][0] = tx; sh_t[w][1] = ty; sh_t[w][2] = tz; sh_t[w][3] = tw;
        sh_v[w] = ttv;
    } else if (lane == 1) {
        sh_a[w][4] = ax; sh_a[w][5] = ay; sh_a[w][6] = az; sh_a[w][7] = aw;
        sh_t[w][4] = tx; sh_t[w][5] = ty; sh_t[w][6] = tz; sh_t[w][7] = tw;
    }
    __syncthreads();

    const int slot = (b * KCH + chunk) * NBLK_S + blockIdx.x;
    if (threadIdx.x < NC) {
        const int c = threadIdx.x;
        float sa = 0.f, st = 0.f;
        #pragma unroll
        for (int w2 = 0; w2 < NW; ++w2) { sa += sh_a[w2][c]; st += sh_t[w2][c]; }
        g_part[c][slot]      = sa;
        g_part[NC + c][slot] = st;
    } else if (threadIdx.x == NC) {
        float s = 0.f;
        #pragma unroll
        for (int w2 = 0; w2 < NW; ++w2) s += sh_v[w2];
        g_part[16][slot] = s;
    }

    // Release: make this block's partials globally visible, then count in.
    __threadfence();
    __syncthreads();
    if (threadIdx.x == 0) atomicAdd(&g_done, 1u);
}

// PDL secondary: one block per batch, 128 threads (small footprint so it can
// co-reside with the primary while spinning).
__global__ __launch_bounds__(128) void final_kernel(const float* __restrict__ count,
                                                    float* __restrict__ out) {
    cudaGridDependencySynchronize();   // returns once all primary blocks triggered

    // Acquire: wait until every primary block has published its partials.
    if (threadIdx.x == 0) {
        while (*(volatile unsigned int*)&g_done != NBLKS) { }
    }
    __syncthreads();
    __threadfence();

    const int b    = blockIdx.x;
    const int w    = threadIdx.x >> 5;     // 4 warps
    const int lane = threadIdx.x & 31;

    __shared__ float sh_fld[16];   // 8 act + 8 tot for this batch
    __shared__ float sh_ttv[4];    // per-warp ttv partials

    // Fields 0..15: warp w reduces fields 4w..4w+3 over this batch's 112 slots
    // (coalesced: consecutive lanes -> consecutive slots).
    #pragma unroll
    for (int k = 0; k < 4; ++k) {
        const int f = 4 * w + k;
        const float* p = &g_part[f][b * SLOTS_PER_B + lane];
        float acc = __ldcg(&p[0]) + __ldcg(&p[32]) + __ldcg(&p[64]);
        if (lane < 16) acc += __ldcg(&p[96]);
        #pragma unroll
        for (int m = 16; m >= 1; m >>= 1)
            acc += __shfl_xor_sync(0xffffffffu, acc, m);
        if (lane == 0) sh_fld[f] = acc;
    }

    // TTV: sum the global ttv row (1792 entries); same value for every block.
    {
        float v = 0.f;
        #pragma unroll
        for (int k = 0; k < NBLKS / 128; ++k)
            v += __ldcg(&g_part[16][k * 128 + threadIdx.x]);
        #pragma unroll
        for (int m = 16; m >= 1; m >>= 1)
            v += __shfl_xor_sync(0xffffffffu, v, m);
        if (lane == 0) sh_ttv[w] = v;
    }
    __syncthreads();

    if (threadIdx.x == 0) {
        float tv = sh_ttv[0] + sh_ttv[1] + sh_ttv[2] + sh_ttv[3];
        float ah = 0.f, bh = 0.f;
        #pragma unroll
        for (int c = 0; c < NC; ++c) {
            const float aa = sh_fld[c];
            const float tt = sh_fld[NC + c];
            float e  = aa - __ldg(&count[b * NC + c]);
            float ae = fabsf(e);
            ah += (ae <= 1.f) ? 0.5f * e * e : (ae - 0.5f);
            float eb  = tt - aa;
            float aeb = fabsf(eb);
            bh += (aeb <= 1.f) ? 0.5f * eb * eb : (aeb - 0.5f);
        }
        out[b] = ah * (1.f / NC) + bh * (1.f / NC) + tv * 0.1f;

        // Self-reset for the next graph replay: last finishing block clears.
        if (atomicAdd(&g_fin, 1u) == NB - 1) {
            g_fin  = 0;
            g_done = 0;
        }
    }
}

extern "C" void kernel_launch(void* const* d_in, const int* in_sizes, int n_in,
                              void* d_out, int out_size) {
    const float* cam    = (const float*)d_in[0];
    const float* count  = (const float*)d_in[1];
    const int*   length = (const int*)d_in[2];
    float*       out    = (float*)d_out;

    dim3 grid(NBLK_S, KCH, NB);
    reduce_kernel<<<grid, BT>>>((const float4*)cam, length);

    // PDL: secondary launches as soon as all primary blocks have fired the
    // (start-of-kernel) trigger; its ramp overlaps the primary's streaming.
    cudaLaunchConfig_t cfg = {};
    cfg.gridDim  = dim3(NB, 1, 1);
    cfg.blockDim = dim3(128, 1, 1);
    cfg.stream   = 0;
    cudaLaunchAttribute attrs[1];
    attrs[0].id = cudaLaunchAttributeProgrammaticStreamSerialization;
    attrs[0].val.programmaticStreamSerializationAllowed = 1;
    cfg.attrs    = attrs;
    cfg.numAttrs = 1;
    cudaLaunchKernelEx(&cfg, final_kernel, count, out);
}

// round 9
// speedup vs baseline: 1.0718x; 1.0718x over previous
#include <cuda_runtime.h>

// Problem constants (fixed shapes from the reference setup)
#define NB   16      // batch
#define NT   128     // time
#define NHWC 25088   // 56*56*8 floats per frame
#define NS4  6272    // NHWC / 4 (float4 strips per frame)
#define NC   8       // channels
#define KCH  4       // time chunks
#define TC   (NT / KCH)             // 32 frames per chunk
#define BT   224                    // block threads; NS4 = 28 * 224 exactly
#define NW   (BT / 32)              // 7 warps
#define NBLK_S (NS4 / BT)           // 28 blocks over the spatial strip
#define SLOTS_PER_B (KCH * NBLK_S)  // 112
#define NBLKS  (NB * SLOTS_PER_B)   // 1792 total blocks
#define NFLD   17                   // 8 act + 8 tot + 1 ttv

// Scratch (no device allocation allowed -> __device__ globals).
// FIELD-MAJOR layout: g_part[field][slot] -> coalesced tail reads.
// Every block writes all its fields every launch => no zeroing needed.
__device__ float g_part[NFLD][NBLKS];

__global__ __launch_bounds__(BT) void reduce_kernel(const float4* __restrict__ x,
                                                    const int* __restrict__ length) {
    // Fire the PDL trigger IMMEDIATELY: the secondary launches and ramps while
    // this grid streams. The secondary's cudaGridDependencySynchronize() is a
    // HW wait for THIS GRID'S FULL COMPLETION (memory visible), so no fences,
    // atomics, or flags are needed here.
    cudaTriggerProgrammaticLaunchCompletion();

    const int s4    = blockIdx.x * BT + threadIdx.x;   // always < NS4
    const int b     = blockIdx.z;
    const int chunk = blockIdx.y;
    const int len   = __ldg(&length[b]);
    const int t0    = chunk * TC;
    const float4* base = x + (size_t)b * NT * NS4 + s4;

    float ax = 0.f, ay = 0.f, az = 0.f, aw = 0.f;   // active sums (4 channels)
    float tx = 0.f, ty = 0.f, tz = 0.f, tw = 0.f;   // total sums
    float ttv = 0.f;
    float px = 0.f, py = 0.f, pz = 0.f, pw = 0.f;   // previous masked frame

    if (t0 > 0 && (t0 - 1) < len) {
        float4 p = __ldcs(&base[(size_t)(t0 - 1) * NS4]);
        px = p.x; py = p.y; pz = p.z; pw = p.w;
    }
    #pragma unroll 8
    for (int t = t0; t < t0 + TC; ++t) {
        float4 v = __ldcs(&base[(size_t)t * NS4]);
        tx += v.x; ty += v.y; tz += v.z; tw += v.w;
        float cx, cy, cz, cw;
        if (t < len) {
            cx = v.x; cy = v.y; cz = v.z; cw = v.w;
            ax += v.x; ay += v.y; az += v.z; aw += v.w;
        } else {
            cx = 0.f; cy = 0.f; cz = 0.f; cw = 0.f;
        }
        if (t > 0) {   // skip only the global t=0 (chunk 0, first iter)
            ttv += fabsf(cx - px) + fabsf(cy - py) + fabsf(cz - pz) + fabsf(cw - pw);
        }
        px = cx; py = cy; pz = cz; pw = cw;
    }

    // --- block reduction ---
    #pragma unroll
    for (int m = 16; m >= 1; m >>= 1)
        ttv += __shfl_xor_sync(0xffffffffu, ttv, m);
    // Parity-preserving reduce: even lanes hold channels 0-3, odd lanes 4-7
    #pragma unroll
    for (int m = 2; m <= 16; m <<= 1) {
        ax += __shfl_xor_sync(0xffffffffu, ax, m);
        ay += __shfl_xor_sync(0xffffffffu, ay, m);
        az += __shfl_xor_sync(0xffffffffu, az, m);
        aw += __shfl_xor_sync(0xffffffffu, aw, m);
        tx += __shfl_xor_sync(0xffffffffu, tx, m);
        ty += __shfl_xor_sync(0xffffffffu, ty, m);
        tz += __shfl_xor_sync(0xffffffffu, tz, m);
        tw += __shfl_xor_sync(0xffffffffu, tw, m);
    }

    __shared__ float sh_a[NW][NC];
    __shared__ float sh_t[NW][NC];
    __shared__ float sh_v[NW];
    const int w = threadIdx.x >> 5, lane = threadIdx.x & 31;
    if (lane == 0) {
        sh_a[w][0] = ax; sh_a[w][1] = ay; sh_a[w][2] = az; sh_a[w][3] = aw;
        sh_t[w][0] = tx; sh_t[w][1] = ty; sh_t[w][2] = tz; sh_t[w][3] = tw;
        sh_v[w] = ttv;
    } else if (lane == 1) {
        sh_a[w][4] = ax; sh_a[w][5] = ay; sh_a[w][6] = az; sh_a[w][7] = aw;
        sh_t[w][4] = tx; sh_t[w][5] = ty; sh_t[w][6] = tz; sh_t[w][7] = tw;
    }
    __syncthreads();

    const int slot = (b * KCH + chunk) * NBLK_S + blockIdx.x;
    if (threadIdx.x < NC) {
        const int c = threadIdx.x;
        float sa = 0.f, st = 0.f;
        #pragma unroll
        for (int w2 = 0; w2 < NW; ++w2) { sa += sh_a[w2][c]; st += sh_t[w2][c]; }
        g_part[c][slot]      = sa;
        g_part[NC + c][slot] = st;
    } else if (threadIdx.x == NC) {
        float s = 0.f;
        #pragma unroll
        for (int w2 = 0; w2 < NW; ++w2) s += sh_v[w2];
        g_part[16][slot] = s;
    }
}

// PDL secondary: launches early (primary triggers at start), ramps while the
// primary streams, then HW-waits for full primary completion. One block per
// batch, 128 threads.
__global__ __launch_bounds__(128) void final_kernel(const float* __restrict__ count,
                                                    float* __restrict__ out) {
    // HW dependency wait: returns when the primary grid has fully completed
    // and all of its memory operations are visible. No polling.
    cudaGridDependencySynchronize();

    const int b    = blockIdx.x;
    const int w    = threadIdx.x >> 5;     // 4 warps
    const int lane = threadIdx.x & 31;

    __shared__ float sh_fld[16];   // 8 act + 8 tot for this batch
    __shared__ float sh_ttv[4];    // per-warp ttv partials

    // Fields 0..15: warp w reduces fields 4w..4w+3 over this batch's 112 slots
    // (coalesced: consecutive lanes -> consecutive slots).
    #pragma unroll
    for (int k = 0; k < 4; ++k) {
        const int f = 4 * w + k;
        const float* p = &g_part[f][b * SLOTS_PER_B + lane];
        float acc = __ldcg(&p[0]) + __ldcg(&p[32]) + __ldcg(&p[64]);
        if (lane < 16) acc += __ldcg(&p[96]);
        #pragma unroll
        for (int m = 16; m >= 1; m >>= 1)
            acc += __shfl_xor_sync(0xffffffffu, acc, m);
        if (lane == 0) sh_fld[f] = acc;
    }

    // TTV: sum the global ttv row (1792 entries); same value for every block.
    {
        float v = 0.f;
        #pragma unroll
        for (int k = 0; k < NBLKS / 128; ++k)
            v += __ldcg(&g_part[16][k * 128 + threadIdx.x]);
        #pragma unroll
        for (int m = 16; m >= 1; m >>= 1)
            v += __shfl_xor_sync(0xffffffffu, v, m);
        if (lane == 0) sh_ttv[w] = v;
    }
    __syncthreads();

    if (threadIdx.x == 0) {
        float tv = sh_ttv[0] + sh_ttv[1] + sh_ttv[2] + sh_ttv[3];
        float ah = 0.f, bh = 0.f;
        #pragma unroll
        for (int c = 0; c < NC; ++c) {
            const float aa = sh_fld[c];
            const float tt = sh_fld[NC + c];
            float e  = aa - __ldg(&count[b * NC + c]);
            float ae = fabsf(e);
            ah += (ae <= 1.f) ? 0.5f * e * e : (ae - 0.5f);
            float eb  = tt - aa;
            float aeb = fabsf(eb);
            bh += (aeb <= 1.f) ? 0.5f * eb * eb : (aeb - 0.5f);
        }
        out[b] = ah * (1.f / NC) + bh * (1.f / NC) + tv * 0.1f;
    }
}

extern "C" void kernel_launch(void* const* d_in, const int* in_sizes, int n_in,
                              void* d_out, int out_size) {
    const float* cam    = (const float*)d_in[0];
    const float* count  = (const float*)d_in[1];
    const int*   length = (const int*)d_in[2];
    float*       out    = (float*)d_out;

    dim3 grid(NBLK_S, KCH, NB);
    reduce_kernel<<<grid, BT>>>((const float4*)cam, length);

    // PDL: secondary launches once all primary blocks fire the start-of-kernel
    // trigger, i.e. during the primary's streaming phase; it then HW-waits for
    // primary completion inside cudaGridDependencySynchronize().
    cudaLaunchConfig_t cfg = {};
    cfg.gridDim  = dim3(NB, 1, 1);
    cfg.blockDim = dim3(128, 1, 1);
    cfg.stream   = 0;
    cudaLaunchAttribute attrs[1];
    attrs[0].id = cudaLaunchAttributeProgrammaticStreamSerialization;
    attrs[0].val.programmaticStreamSerializationAllowed = 1;
    cfg.attrs    = attrs;
    cfg.numAttrs = 1;
    cudaLaunchKernelEx(&cfg, final_kernel, count, out);
}

// round 10
// speedup vs baseline: 1.0975x; 1.0240x over previous
#include <cuda_runtime.h>

// Problem constants (fixed shapes from the reference setup)
#define NB   16      // batch
#define NT   128     // time
#define NHWC 25088   // 56*56*8 floats per frame
#define NS4  6272    // NHWC / 4 (float4 strips per frame)
#define NC   8       // channels
#define KCH  2       // time chunks (896 total blocks -> whole grid fits in ONE wave)
#define TC   (NT / KCH)             // 64 frames per chunk
#define BT   224                    // block threads; NS4 = 28 * 224 exactly
#define NW   (BT / 32)              // 7 warps
#define NBLK_S (NS4 / BT)           // 28 blocks over the spatial strip
#define SLOTS_PER_B (KCH * NBLK_S)  // 56
#define NBLKS  (NB * SLOTS_PER_B)   // 896 total blocks
#define NFLD   17                   // 8 act + 8 tot + 1 ttv

// Scratch (no device allocation allowed -> __device__ globals).
// FIELD-MAJOR layout: g_part[field][slot] -> coalesced tail reads.
// Every block writes all its fields every launch => no zeroing needed.
__device__ float g_part[NFLD][NBLKS];

__global__ __launch_bounds__(BT) void reduce_kernel(const float4* __restrict__ x,
                                                    const int* __restrict__ length) {
    // Fire the PDL trigger IMMEDIATELY: the secondary launches and ramps while
    // this grid streams; its cudaGridDependencySynchronize() HW-waits for this
    // grid's full completion (memory visible) -> no fences/atomics needed here.
    cudaTriggerProgrammaticLaunchCompletion();

    const int s4    = blockIdx.x * BT + threadIdx.x;   // always < NS4
    const int b     = blockIdx.z;
    const int chunk = blockIdx.y;
    const int len   = __ldg(&length[b]);
    const int t0    = chunk * TC;
    const float4* base = x + (size_t)b * NT * NS4 + s4;

    float ax = 0.f, ay = 0.f, az = 0.f, aw = 0.f;   // active sums (4 channels)
    float tx = 0.f, ty = 0.f, tz = 0.f, tw = 0.f;   // total sums
    float ttv = 0.f;
    float px = 0.f, py = 0.f, pz = 0.f, pw = 0.f;   // previous masked frame

    if (t0 > 0 && (t0 - 1) < len) {
        float4 p = __ldcs(&base[(size_t)(t0 - 1) * NS4]);
        px = p.x; py = p.y; pz = p.z; pw = p.w;
    }
    #pragma unroll 8
    for (int t = t0; t < t0 + TC; ++t) {
        float4 v = __ldcs(&base[(size_t)t * NS4]);
        tx += v.x; ty += v.y; tz += v.z; tw += v.w;
        float cx, cy, cz, cw;
        if (t < len) {
            cx = v.x; cy = v.y; cz = v.z; cw = v.w;
            ax += v.x; ay += v.y; az += v.z; aw += v.w;
        } else {
            cx = 0.f; cy = 0.f; cz = 0.f; cw = 0.f;
        }
        if (t > 0) {   // skip only the global t=0 (chunk 0, first iter)
            ttv += fabsf(cx - px) + fabsf(cy - py) + fabsf(cz - pz) + fabsf(cw - pw);
        }
        px = cx; py = cy; pz = cz; pw = cw;
    }

    // --- block reduction ---
    #pragma unroll
    for (int m = 16; m >= 1; m >>= 1)
        ttv += __shfl_xor_sync(0xffffffffu, ttv, m);
    // Parity-preserving reduce: even lanes hold channels 0-3, odd lanes 4-7
    #pragma unroll
    for (int m = 2; m <= 16; m <<= 1) {
        ax += __shfl_xor_sync(0xffffffffu, ax, m);
        ay += __shfl_xor_sync(0xffffffffu, ay, m);
        az += __shfl_xor_sync(0xffffffffu, az, m);
        aw += __shfl_xor_sync(0xffffffffu, aw, m);
        tx += __shfl_xor_sync(0xffffffffu, tx, m);
        ty += __shfl_xor_sync(0xffffffffu, ty, m);
        tz += __shfl_xor_sync(0xffffffffu, tz, m);
        tw += __shfl_xor_sync(0xffffffffu, tw, m);
    }

    __shared__ float sh_a[NW][NC];
    __shared__ float sh_t[NW][NC];
    __shared__ float sh_v[NW];
    const int w = threadIdx.x >> 5, lane = threadIdx.x & 31;
    if (lane == 0) {
        sh_a[w][0] = ax; sh_a[w][1] = ay; sh_a[w][2] = az; sh_a[w][3] = aw;
        sh_t[w][0] = tx; sh_t[w][1] = ty; sh_t[w][2] = tz; sh_t[w][3] = tw;
        sh_v[w] = ttv;
    } else if (lane == 1) {
        sh_a[w][4] = ax; sh_a[w][5] = ay; sh_a[w][6] = az; sh_a[w][7] = aw;
        sh_t[w][4] = tx; sh_t[w][5] = ty; sh_t[w][6] = tz; sh_t[w][7] = tw;
    }
    __syncthreads();

    const int slot = (b * KCH + chunk) * NBLK_S + blockIdx.x;
    if (threadIdx.x < NC) {
        const int c = threadIdx.x;
        float sa = 0.f, st = 0.f;
        #pragma unroll
        for (int w2 = 0; w2 < NW; ++w2) { sa += sh_a[w2][c]; st += sh_t[w2][c]; }
        g_part[c][slot]      = sa;
        g_part[NC + c][slot] = st;
    } else if (threadIdx.x == NC) {
        float s = 0.f;
        #pragma unroll
        for (int w2 = 0; w2 < NW; ++w2) s += sh_v[w2];
        g_part[16][slot] = s;
    }
}

// PDL secondary: launches early (primary triggers at start), ramps while the
// primary streams, then HW-waits for full primary completion. One block per
// batch, 128 threads.
__global__ __launch_bounds__(128) void final_kernel(const float* __restrict__ count,
                                                    float* __restrict__ out) {
    cudaGridDependencySynchronize();

    const int b    = blockIdx.x;
    const int w    = threadIdx.x >> 5;     // 4 warps
    const int lane = threadIdx.x & 31;

    __shared__ float sh_fld[16];   // 8 act + 8 tot for this batch
    __shared__ float sh_ttv[4];    // per-warp ttv partials

    // Fields 0..15: warp w reduces fields 4w..4w+3 over this batch's 56 slots
    // (coalesced: consecutive lanes -> consecutive slots). 56 = 32 + 24.
    #pragma unroll
    for (int k = 0; k < 4; ++k) {
        const int f = 4 * w + k;
        const float* p = &g_part[f][b * SLOTS_PER_B + lane];
        float acc = __ldcg(&p[0]);
        if (lane < 24) acc += __ldcg(&p[32]);
        #pragma unroll
        for (int m = 16; m >= 1; m >>= 1)
            acc += __shfl_xor_sync(0xffffffffu, acc, m);
        if (lane == 0) sh_fld[f] = acc;
    }

    // TTV: sum the global ttv row (896 entries); same value for every block.
    {
        float v = 0.f;
        #pragma unroll
        for (int k = 0; k < NBLKS / 128; ++k)
            v += __ldcg(&g_part[16][k * 128 + threadIdx.x]);
        #pragma unroll
        for (int m = 16; m >= 1; m >>= 1)
            v += __shfl_xor_sync(0xffffffffu, v, m);
        if (lane == 0) sh_ttv[w] = v;
    }
    __syncthreads();

    if (threadIdx.x == 0) {
        float tv = sh_ttv[0] + sh_ttv[1] + sh_ttv[2] + sh_ttv[3];
        float ah = 0.f, bh = 0.f;
        #pragma unroll
        for (int c = 0; c < NC; ++c) {
            const float aa = sh_fld[c];
            const float tt = sh_fld[NC + c];
            float e  = aa - __ldg(&count[b * NC + c]);
            float ae = fabsf(e);
            ah += (ae <= 1.f) ? 0.5f * e * e : (ae - 0.5f);
            float eb  = tt - aa;
            float aeb = fabsf(eb);
            bh += (aeb <= 1.f) ? 0.5f * eb * eb : (aeb - 0.5f);
        }
        out[b] = ah * (1.f / NC) + bh * (1.f / NC) + tv * 0.1f;
    }
}

extern "C" void kernel_launch(void* const* d_in, const int* in_sizes, int n_in,
                              void* d_out, int out_size) {
    const float* cam    = (const float*)d_in[0];
    const float* count  = (const float*)d_in[1];
    const int*   length = (const int*)d_in[2];
    float*       out    = (float*)d_out;

    dim3 grid(NBLK_S, KCH, NB);
    reduce_kernel<<<grid, BT>>>((const float4*)cam, length);

    cudaLaunchConfig_t cfg = {};
    cfg.gridDim  = dim3(NB, 1, 1);
    cfg.blockDim = dim3(128, 1, 1);
    cfg.stream   = 0;
    cudaLaunchAttribute attrs[1];
    attrs[0].id = cudaLaunchAttributeProgrammaticStreamSerialization;
    attrs[0].val.programmaticStreamSerializationAllowed = 1;
    cfg.attrs    = attrs;
    cfg.numAttrs = 1;
    cudaLaunchKernelEx(&cfg, final_kernel, count, out);
}